// round 2
// baseline (speedup 1.0000x reference)
#include <cuda_runtime.h>
#include <cstdint>

#define N_ANCH 36864
#define N_PAD  65536
#define PRE    6000
#define NWORDS 94      /* ceil(6000/64) */
#define POST   300
#define NMS_T  0.7f
#define NEG_INF_F (-1e9f)

// ---------------- scratch (static device globals; no allocation) ----------------
__device__ unsigned long long g_keys[N_PAD];            // 512 KB
__device__ float4             g_boxes[N_ANCH];          // 576 KB (decoded+clipped)
__device__ float4             g_boxes_s[PRE];           // top-6000 boxes, score order
__device__ unsigned char      g_valid_s[PRE];
__device__ unsigned long long g_mask[PRE * NWORDS];     // 4.5 MB suppression bitmask

// ---------------- 1. decode + clip + valid + sort key ----------------
__global__ void decode_kernel(const float* __restrict__ anchors,
                              const float* __restrict__ cls,
                              const float* __restrict__ reg,
                              const int* __restrict__ img_w_p,
                              const int* __restrict__ img_h_p,
                              int have_wh)
{
    int i = blockIdx.x * blockDim.x + threadIdx.x;
    if (i >= N_PAD) return;
    if (i >= N_ANCH) { g_keys[i] = ~0ull; return; }   // pad keys sort last

    float a0 = anchors[4*i+0], a1 = anchors[4*i+1];
    float a2 = anchors[4*i+2], a3 = anchors[4*i+3];
    float r0 = reg[4*i+0], r1 = reg[4*i+1], r2 = reg[4*i+2], r3 = reg[4*i+3];

    float w  = __fsub_rn(a2, a0);
    float h  = __fsub_rn(a3, a1);
    float cx = __fadd_rn(a0, __fmul_rn(0.5f, w));
    float cy = __fadd_rn(a1, __fmul_rn(0.5f, h));
    float pcx = __fadd_rn(__fmul_rn(r0, w), cx);
    float pcy = __fadd_rn(__fmul_rn(r1, h), cy);
    float pw  = __fmul_rn(expf(r2), w);
    float ph  = __fmul_rn(expf(r3), h);

    float b0 = __fsub_rn(pcx, __fmul_rn(0.5f, pw));
    float b1 = __fsub_rn(pcy, __fmul_rn(0.5f, ph));
    float b2 = __fadd_rn(pcx, __fmul_rn(0.5f, pw));
    float b3 = __fadd_rn(pcy, __fmul_rn(0.5f, ph));

    float H = have_wh ? (float)(*img_h_p) : 1024.0f;
    float W = have_wh ? (float)(*img_w_p) : 1024.0f;
    // reference: cols 0,2 clipped by img_h; cols 1,3 by img_w
    b0 = fminf(fmaxf(b0, 0.0f), H);
    b2 = fminf(fmaxf(b2, 0.0f), H);
    b1 = fminf(fmaxf(b1, 0.0f), W);
    b3 = fminf(fmaxf(b3, 0.0f), W);

    bool valid = (__fsub_rn(b2, b0) >= 16.0f) && (__fsub_rn(b3, b1) >= 16.0f);
    float s = valid ? cls[i] : NEG_INF_F;

    g_boxes[i] = make_float4(b0, b1, b2, b3);

    // stable descending sort key: (descending score bits, ascending index)
    unsigned int bits = __float_as_uint(s);
    unsigned int asc  = (bits & 0x80000000u) ? ~bits : (bits | 0x80000000u); // order-preserving
    unsigned int desc = ~asc;
    g_keys[i] = ((unsigned long long)desc << 16) | (unsigned int)i;
}

// ---------------- 2. bitonic sort of 65536 u64 keys ----------------
// 2a. per-tile full sort (tiles of 4096, directions from GLOBAL index -> tiles
//     come out alternately asc/desc = valid bitonic sequences of 8192)
__global__ void sort_local_kernel()
{
    __shared__ unsigned long long s[4096];
    int base = blockIdx.x * 4096;
    for (int t = threadIdx.x; t < 4096; t += 1024) s[t] = g_keys[base + t];
    __syncthreads();
    for (int k = 2; k <= 4096; k <<= 1) {
        for (int j = k >> 1; j > 0; j >>= 1) {
            for (int p = threadIdx.x; p < 2048; p += 1024) {
                int i   = ((p & ~(j - 1)) << 1) | (p & (j - 1));
                int ixj = i | j;
                bool asc = (((base + i) & k) == 0);
                unsigned long long a = s[i], b = s[ixj];
                bool sw = asc ? (a > b) : (a < b);
                if (sw) { s[i] = b; s[ixj] = a; }
            }
            __syncthreads();
        }
    }
    for (int t = threadIdx.x; t < 4096; t += 1024) g_keys[base + t] = s[t];
}

// 2b. one global compare-exchange step (stride >= 4096)
__global__ void sort_global_kernel(int k, int j)
{
    int t = blockIdx.x * blockDim.x + threadIdx.x;   // 32768 threads
    int i   = ((t & ~(j - 1)) << 1) | (t & (j - 1));
    int ixj = i | j;
    bool asc = ((i & k) == 0);
    unsigned long long a = g_keys[i], b = g_keys[ixj];
    bool sw = asc ? (a > b) : (a < b);
    if (sw) { g_keys[i] = b; g_keys[ixj] = a; }
}

// 2c. finish strides 2048..1 for merge level k (>=8192) in shared memory
__global__ void sort_finish_kernel(int k)
{
    __shared__ unsigned long long s[4096];
    int base = blockIdx.x * 4096;
    for (int t = threadIdx.x; t < 4096; t += 1024) s[t] = g_keys[base + t];
    __syncthreads();
    for (int j = 2048; j > 0; j >>= 1) {
        for (int p = threadIdx.x; p < 2048; p += 1024) {
            int i   = ((p & ~(j - 1)) << 1) | (p & (j - 1));
            int ixj = i | j;
            bool asc = (((base + i) & k) == 0);
            unsigned long long a = s[i], b = s[ixj];
            bool sw = asc ? (a > b) : (a < b);
            if (sw) { s[i] = b; s[ixj] = a; }
        }
        __syncthreads();
    }
    for (int t = threadIdx.x; t < 4096; t += 1024) g_keys[base + t] = s[t];
}

// ---------------- 3. gather top-6000 ----------------
__global__ void gather_kernel()
{
    int t = blockIdx.x * blockDim.x + threadIdx.x;
    if (t >= PRE) return;
    unsigned long long key = g_keys[t];
    int idx = (int)(key & 0xFFFFull);
    g_boxes_s[t] = g_boxes[idx];
    unsigned int desc = (unsigned int)(key >> 16);
    // valid  <=>  masked score >= 0  <=>  desc < 0x80000000
    g_valid_s[t] = (desc < 0x80000000u) ? 1 : 0;
}

// ---------------- 4. NMS suppression bitmask (6000 x 94 u64) ----------------
__global__ void mask_kernel()
{
    __shared__ float4 cb[64];
    __shared__ float  ca[64];
    int tid = threadIdx.x;
    int jb  = blockIdx.y;
    int j0  = jb * 64;
    int jj  = j0 + tid;
    float4 b = (jj < PRE) ? g_boxes_s[jj] : make_float4(0.f, 0.f, 0.f, 0.f);
    cb[tid] = b;
    ca[tid] = __fmul_rn(__fsub_rn(b.z, b.x), __fsub_rn(b.w, b.y));
    __syncthreads();

    int i = blockIdx.x * 64 + tid;
    if (i >= PRE) return;
    float4 bi = g_boxes_s[i];
    float  ai = __fmul_rn(__fsub_rn(bi.z, bi.x), __fsub_rn(bi.w, bi.y));

    unsigned long long m = 0;
#pragma unroll 8
    for (int s = 0; s < 64; s++) {
        int j = j0 + s;
        float4 bj = cb[s];
        float xx1 = fmaxf(bi.x, bj.x);
        float yy1 = fmaxf(bi.y, bj.y);
        float xx2 = fminf(bi.z, bj.z);
        float yy2 = fminf(bi.w, bj.w);
        float iw  = fmaxf(__fsub_rn(xx2, xx1), 0.0f);
        float ih  = fmaxf(__fsub_rn(yy2, yy1), 0.0f);
        float inter = __fmul_rn(iw, ih);
        // exact reference op order: ((ai + aj) - inter) + 1e-9, IEEE divide
        float den = __fadd_rn(__fsub_rn(__fadd_rn(ai, ca[s]), inter), 1e-9f);
        float iou = __fdiv_rn(inter, den);
        if ((iou > NMS_T) && (j > i)) m |= (1ull << s);
    }
    g_mask[i * NWORDS + jb] = m;
}

// ---------------- 5. greedy scan (chunked) + output ----------------
__global__ void scan_kernel(float* __restrict__ out)
{
    __shared__ unsigned long long s_rem[NWORDS];
    __shared__ unsigned long long s_intra[64];
    __shared__ unsigned long long s_alive;
    __shared__ int s_kept;
    int tid = threadIdx.x;

    // zero-init output (harness poisons it)
    for (int t = tid; t < POST * 4; t += blockDim.x) out[t] = 0.0f;

    if (tid < NWORDS) {
        unsigned long long w = 0;
        for (int b = 0; b < 64; b++) {
            int idx = tid * 64 + b;
            if (idx >= PRE || g_valid_s[idx] == 0) w |= (1ull << b);
        }
        s_rem[tid] = w;
    }
    if (tid == 0) s_kept = 0;
    __syncthreads();

    for (int c = 0; c < NWORDS; c++) {
        if (tid < 64) {
            int i = c * 64 + tid;
            s_intra[tid] = (i < PRE) ? g_mask[i * NWORDS + c] : 0ull;
        }
        __syncthreads();

        if (tid == 0) {
            unsigned long long rem = s_rem[c];
            unsigned long long alive = 0;
            int kept = s_kept;
            for (int b = 0; b < 64; b++) {
                if (!((rem >> b) & 1ull)) {
                    alive |= (1ull << b);
                    rem |= s_intra[b];           // suppress later in-chunk boxes
                    if (kept < POST) {
                        float4 bx = g_boxes_s[c * 64 + b];
                        reinterpret_cast<float4*>(out)[kept] = bx;
                    }
                    kept++;
                }
            }
            s_alive = alive;
            s_kept  = kept;
        }
        __syncthreads();

        if (s_kept >= POST) break;               // nothing later can affect output

        unsigned long long alive = s_alive;
        if (tid < NWORDS && tid > c && alive) {
            unsigned long long acc = s_rem[tid];
            unsigned long long a = alive;
            while (a) {
                int b = __ffsll((long long)a) - 1;
                a &= a - 1;
                acc |= g_mask[(c * 64 + b) * NWORDS + tid];
            }
            s_rem[tid] = acc;
        }
        __syncthreads();
    }
}

// ---------------- launch ----------------
extern "C" void kernel_launch(void* const* d_in, const int* in_sizes, int n_in,
                              void* d_out, int out_size)
{
    const float* anchors = (const float*)d_in[0];
    const float* cls     = (const float*)d_in[1];
    const float* reg     = (const float*)d_in[2];
    const int*   img_w   = (n_in > 3) ? (const int*)d_in[3] : nullptr;
    const int*   img_h   = (n_in > 4) ? (const int*)d_in[4] : nullptr;
    int have_wh = (n_in > 4) ? 1 : 0;

    decode_kernel<<<N_PAD / 256, 256>>>(anchors, cls, reg, img_w, img_h, have_wh);

    sort_local_kernel<<<16, 1024>>>();
    for (int k = 8192; k <= 65536; k <<= 1) {
        for (int j = k >> 1; j >= 4096; j >>= 1)
            sort_global_kernel<<<128, 256>>>(k, j);
        sort_finish_kernel<<<16, 1024>>>(k);
    }

    gather_kernel<<<(PRE + 255) / 256, 256>>>();
    mask_kernel<<<dim3(NWORDS, NWORDS), 64>>>();
    scan_kernel<<<1, 128>>>((float*)d_out);
}

// round 3
// speedup vs baseline: 1.2334x; 1.2334x over previous
#include <cuda_runtime.h>
#include <cstdint>

#define N_ANCH 36864
#define PRE    6000
#define NWORDS 94      /* ceil(6000/64) */
#define POST   300
#define NMS_T  0.7f
#define NEG_INF_F (-1e9f)
#define NBINS  2048

// ---------------- scratch (static device globals; no allocation) ----------------
__device__ float4             g_boxes[N_ANCH];          // decoded+clipped boxes
__device__ unsigned long long g_keyfull[N_ANCH];        // (desc<<16)|idx
__device__ int                g_hist[NBINS];            // zero-init at load; plan re-zeroes
__device__ int                g_bin_base[NBINS];
__device__ int                g_bin_fill[NBINS];        // zero-init at load; plan re-zeroes
__device__ int                g_thresh_bin;
__device__ int                g_cand_total;
__device__ unsigned long long g_cand[N_ANCH];
__device__ float4             g_boxes_s[PRE];           // top-6000 boxes, score order
__device__ unsigned long long g_invalid_words[NWORDS];  // suppressed-at-start bits
__device__ unsigned long long g_mask[PRE * NWORDS];     // suppression bitmask (upper tri)

// ---------------- 1. decode + clip + valid + key + histogram ----------------
__global__ void decode_kernel(const float* __restrict__ anchors,
                              const float* __restrict__ cls,
                              const float* __restrict__ reg,
                              const int* __restrict__ img_w_p,
                              const int* __restrict__ img_h_p,
                              int have_wh)
{
    int i = blockIdx.x * blockDim.x + threadIdx.x;
    if (i >= N_ANCH) return;

    float a0 = anchors[4*i+0], a1 = anchors[4*i+1];
    float a2 = anchors[4*i+2], a3 = anchors[4*i+3];
    float r0 = reg[4*i+0], r1 = reg[4*i+1], r2 = reg[4*i+2], r3 = reg[4*i+3];

    float w  = __fsub_rn(a2, a0);
    float h  = __fsub_rn(a3, a1);
    float cx = __fadd_rn(a0, __fmul_rn(0.5f, w));
    float cy = __fadd_rn(a1, __fmul_rn(0.5f, h));
    float pcx = __fadd_rn(__fmul_rn(r0, w), cx);
    float pcy = __fadd_rn(__fmul_rn(r1, h), cy);
    float pw  = __fmul_rn(expf(r2), w);
    float ph  = __fmul_rn(expf(r3), h);

    float b0 = __fsub_rn(pcx, __fmul_rn(0.5f, pw));
    float b1 = __fsub_rn(pcy, __fmul_rn(0.5f, ph));
    float b2 = __fadd_rn(pcx, __fmul_rn(0.5f, pw));
    float b3 = __fadd_rn(pcy, __fmul_rn(0.5f, ph));

    float H = have_wh ? (float)(*img_h_p) : 1024.0f;
    float W = have_wh ? (float)(*img_w_p) : 1024.0f;
    // reference: cols 0,2 clipped by img_h; cols 1,3 by img_w
    b0 = fminf(fmaxf(b0, 0.0f), H);
    b2 = fminf(fmaxf(b2, 0.0f), H);
    b1 = fminf(fmaxf(b1, 0.0f), W);
    b3 = fminf(fmaxf(b3, 0.0f), W);

    bool valid = (__fsub_rn(b2, b0) >= 16.0f) && (__fsub_rn(b3, b1) >= 16.0f);
    float s = valid ? cls[i] : NEG_INF_F;

    g_boxes[i] = make_float4(b0, b1, b2, b3);

    // stable descending sort key: smaller desc = higher score; idx breaks ties (stable)
    unsigned int bits = __float_as_uint(s);
    unsigned int asc  = (bits & 0x80000000u) ? ~bits : (bits | 0x80000000u);
    unsigned int desc = ~asc;
    unsigned long long key = ((unsigned long long)desc << 16) | (unsigned int)i;
    g_keyfull[i] = key;
    atomicAdd(&g_hist[desc >> 21], 1);
}

// ---------------- 2. plan: prefix-sum bins, find threshold, reset state ----------------
__global__ void plan_kernel()
{
    __shared__ int sp[1024];
    __shared__ int s_thresh;
    int t = threadIdx.x;
    if (t == 0) s_thresh = 0x7FFFFFFF;

    int h0 = g_hist[2*t], h1 = g_hist[2*t+1];
    int p = h0 + h1;
    sp[t] = p;
    __syncthreads();
    for (int off = 1; off < 1024; off <<= 1) {
        int v = (t >= off) ? sp[t - off] : 0;
        __syncthreads();
        sp[t] += v;
        __syncthreads();
    }
    int pincl = sp[t];
    int pbase = pincl - p;                 // exclusive prefix over bin pairs
    g_bin_base[2*t]   = pbase;
    g_bin_base[2*t+1] = pbase + h0;
    if (pbase + h0 >= PRE) atomicMin(&s_thresh, 2*t);       // inclusive cum of bin 2t
    if (pincl     >= PRE) atomicMin(&s_thresh, 2*t + 1);
    __syncthreads();
    if (t == 0) {
        int tb = s_thresh;
        g_thresh_bin = tb;
        g_cand_total = g_bin_base[tb] + g_hist[tb];
    }
    __syncthreads();   // t0 must read g_hist before zeroing
    g_hist[2*t] = 0;  g_hist[2*t+1] = 0;
    g_bin_fill[2*t] = 0;  g_bin_fill[2*t+1] = 0;
    if (t < NWORDS)
        g_invalid_words[t] = (t == NWORDS-1) ? ~((1ull << 48) - 1) : 0ull;  // ranks >= 6000
}

// ---------------- 3. scatter candidates into per-bin segments ----------------
__global__ void scatter_kernel()
{
    int i = blockIdx.x * blockDim.x + threadIdx.x;
    if (i >= N_ANCH) return;
    unsigned long long key = g_keyfull[i];
    int bin = (int)(key >> 37);
    if (bin <= g_thresh_bin) {
        int pos = g_bin_base[bin] + atomicAdd(&g_bin_fill[bin], 1);
        g_cand[pos] = key;
    }
}

// ---------------- 4. exact rank within bin + gather boxes ----------------
__global__ void rank_kernel()
{
    int c = blockIdx.x * blockDim.x + threadIdx.x;
    int tot = g_cand_total;
    if (c >= tot) return;
    unsigned long long key = g_cand[c];
    int bin = (int)(key >> 37);
    int b0 = g_bin_base[bin];
    int b1 = b0 + g_bin_fill[bin];
    int rank = b0;
    for (int j = b0; j < b1; j++)
        if (g_cand[j] < key) rank++;
    if (rank < PRE) {
        int idx = (int)(key & 0xFFFFull);
        g_boxes_s[rank] = g_boxes[idx];
        unsigned int desc = (unsigned int)(key >> 16);
        if (desc & 0x80000000u)   // invalid box -> pre-suppressed
            atomicOr(&g_invalid_words[rank >> 6], 1ull << (rank & 63));
    }
}

// ---------------- 5. NMS suppression bitmask (upper-triangle blocks only) ----------------
__global__ void mask_kernel()
{
    if (blockIdx.y < blockIdx.x) return;   // lower triangle never read by scan
    __shared__ float4 cb[64];
    __shared__ float  ca[64];
    int tid = threadIdx.x;
    int jb  = blockIdx.y;
    int j0  = jb * 64;
    int jj  = j0 + tid;
    float4 b = (jj < PRE) ? g_boxes_s[jj] : make_float4(0.f, 0.f, 0.f, 0.f);
    cb[tid] = b;
    ca[tid] = __fmul_rn(__fsub_rn(b.z, b.x), __fsub_rn(b.w, b.y));
    __syncthreads();

    int i = blockIdx.x * 64 + tid;
    if (i >= PRE) return;
    float4 bi = g_boxes_s[i];
    float  ai = __fmul_rn(__fsub_rn(bi.z, bi.x), __fsub_rn(bi.w, bi.y));

    unsigned long long m = 0;
#pragma unroll 8
    for (int s = 0; s < 64; s++) {
        int j = j0 + s;
        float4 bj = cb[s];
        float xx1 = fmaxf(bi.x, bj.x);
        float yy1 = fmaxf(bi.y, bj.y);
        float xx2 = fminf(bi.z, bj.z);
        float yy2 = fminf(bi.w, bj.w);
        float iw  = fmaxf(__fsub_rn(xx2, xx1), 0.0f);
        float ih  = fmaxf(__fsub_rn(yy2, yy1), 0.0f);
        float inter = __fmul_rn(iw, ih);
        // exact reference op order: ((ai + aj) - inter) + 1e-9, IEEE divide
        float den = __fadd_rn(__fsub_rn(__fadd_rn(ai, ca[s]), inter), 1e-9f);
        float iou = __fdiv_rn(inter, den);
        if ((iou > NMS_T) && (j > i)) m |= (1ull << s);
    }
    g_mask[i * NWORDS + jb] = m;
}

// ---------------- 6. greedy scan (chunked, parallel propagation) + output ----------------
__global__ void scan_kernel(float* __restrict__ out)
{
    __shared__ unsigned long long s_rem[NWORDS];
    __shared__ unsigned long long s_intra[64];
    __shared__ unsigned char     s_aliveb[64];
    __shared__ unsigned short    s_keep[POST];
    __shared__ int s_n, s_kept;
    int tid = threadIdx.x;

    if (tid < NWORDS) s_rem[tid] = g_invalid_words[tid];
    if (tid == 0) s_kept = 0;
    __syncthreads();

    for (int c = 0; c < NWORDS; c++) {
        if (tid < 64) {
            int i = c * 64 + tid;
            s_intra[tid] = (i < PRE) ? g_mask[i * NWORDS + c] : 0ull;
        }
        __syncthreads();

        if (tid == 0) {
            unsigned long long rem = s_rem[c];
            int n = 0;
            int kept = s_kept;
            unsigned long long m = ~rem;
            while (m) {
                int b = __ffsll((long long)m) - 1;    // smallest alive index
                s_keep[kept] = (unsigned short)(c * 64 + b);
                kept++;
                s_aliveb[n++] = (unsigned char)b;
                if (kept >= POST) break;
                rem |= s_intra[b];
                m = ~rem & (~0ull << (b + 1));        // alive bits strictly above b
            }
            s_n = n;
            s_kept = kept;
        }
        __syncthreads();

        if (s_kept >= POST) break;                    // output fixed; later chunks irrelevant
        if (c == NWORDS - 1) break;

        // parallel propagation: (alive bit) x (future word)
        int n  = s_n;
        int nw = NWORDS - 1 - c;
        for (int p = tid; p < n * nw; p += 1024) {
            int bi = p / nw;
            int w  = c + 1 + p - bi * nw;
            unsigned long long v = g_mask[(c * 64 + s_aliveb[bi]) * NWORDS + w];
            atomicOr(&s_rem[w], v);
        }
        __syncthreads();
    }
    __syncthreads();

    // write output: kept boxes in order, zero-pad the tail
    int kept = s_kept;
    if (tid < POST) {
        float4 v = make_float4(0.f, 0.f, 0.f, 0.f);
        if (tid < kept) v = g_boxes_s[s_keep[tid]];
        reinterpret_cast<float4*>(out)[tid] = v;
    }
}

// ---------------- launch ----------------
extern "C" void kernel_launch(void* const* d_in, const int* in_sizes, int n_in,
                              void* d_out, int out_size)
{
    const float* anchors = (const float*)d_in[0];
    const float* cls     = (const float*)d_in[1];
    const float* reg     = (const float*)d_in[2];
    const int*   img_w   = (n_in > 3) ? (const int*)d_in[3] : nullptr;
    const int*   img_h   = (n_in > 4) ? (const int*)d_in[4] : nullptr;
    int have_wh = (n_in > 4) ? 1 : 0;

    decode_kernel<<<(N_ANCH + 255) / 256, 256>>>(anchors, cls, reg, img_w, img_h, have_wh);
    plan_kernel<<<1, 1024>>>();
    scatter_kernel<<<(N_ANCH + 255) / 256, 256>>>();
    rank_kernel<<<(N_ANCH + 255) / 256, 256>>>();
    mask_kernel<<<dim3(NWORDS, NWORDS), 64>>>();
    scan_kernel<<<1, 1024>>>((float*)d_out);
}